// round 5
// baseline (speedup 1.0000x reference)
#include <cuda_runtime.h>

#define BATCH   4
#define NPTS    8192
#define THREADS 256
#define QPT     4
#define QTILE   (THREADS * QPT)     // 1024 queries per block
#define JSPLIT  8
#define JCHUNK  (NPTS / JSPLIT)     // 1024 ref points per block (fully smem-resident)
#define SEG     64                  // segment granularity for argmin recovery
#define NSEG    (JCHUNK / SEG)      // 16

typedef unsigned long long ull;

// Partial results: packed (dist_bits<<32)|global_j per (dir, jc, b*N+q). 4 MB.
__device__ ull g_part[2][JSPLIT][BATCH * NPTS];

// ---- packed fp32x2 helpers (sm_103a). Explicit .rn, no FMA contraction. ----
static __device__ __forceinline__ ull pk2(float lo, float hi) {
    ull r; asm("mov.b64 %0, {%1, %2};" : "=l"(r) : "f"(lo), "f"(hi)); return r;
}
static __device__ __forceinline__ void up2(ull v, float& lo, float& hi) {
    asm("mov.b64 {%0, %1}, %2;" : "=f"(lo), "=f"(hi) : "l"(v));
}
static __device__ __forceinline__ ull add2(ull a, ull b) {
    ull r; asm("add.rn.f32x2 %0, %1, %2;" : "=l"(r) : "l"(a), "l"(b)); return r;
}
static __device__ __forceinline__ ull mul2(ull a, ull b) {
    ull r; asm("mul.rn.f32x2 %0, %1, %2;" : "=l"(r) : "l"(a), "l"(b)); return r;
}

// Packed squared distance for one ref against one packed query pair.
// EXACTLY the pass-1 instruction sequence: (dx*dx + dy*dy) + dz*dz, all .rn f32x2.
static __device__ __forceinline__ ull pdist2(ull qx, ull qy, ull qz,
                                             ull nx, ull ny, ull nz) {
    ull dx = add2(qx, nx), dy = add2(qy, ny), dz = add2(qz, nz);
    return add2(add2(mul2(dx, dx), mul2(dy, dy)), mul2(dz, dz));
}

// One fused kernel: blockIdx.z selects direction.
// Grid: x = (NPTS/QTILE)*JSPLIT = 64, y = BATCH, z = 2.
__global__ void __launch_bounds__(THREADS)
chamfer_kernel(const float* __restrict__ xyz1, const float* __restrict__ xyz2)
{
    // Negated, lane-duplicated SoA ref tiles: sx[j] = pk2(-x_j, -x_j). 24 KB.
    __shared__ ull sx[JCHUNK], sy[JCHUNK], sz[JCHUNK];

    const int dir = blockIdx.z;
    const int b   = blockIdx.y;
    const int qt  = blockIdx.x / JSPLIT;
    const int jc  = blockIdx.x % JSPLIT;
    const int tid = threadIdx.x;

    const float* qpts = dir ? xyz2 : xyz1;
    const float* rpts = dir ? xyz1 : xyz2;
    const float* qb = qpts + (size_t)b * NPTS * 3;
    const float* rb = rpts + (size_t)b * NPTS * 3;

    const int jbase = jc * JCHUNK;

    // ---- Stage JCHUNK refs (negated, duplicated) ----
    for (int l = tid; l < JCHUNK; l += THREADS) {
        const float* r = rb + (size_t)(jbase + l) * 3;
        float nx = -r[0], ny = -r[1], nz = -r[2];
        sx[l] = pk2(nx, nx);
        sy[l] = pk2(ny, ny);
        sz[l] = pk2(nz, nz);
    }

    // ---- Load 4 queries per thread (strided), pack as f32x2 pairs ----
    const int q0 = qt * QTILE + tid;
    float qxs[QPT], qys[QPT], qzs[QPT];
#pragma unroll
    for (int k = 0; k < QPT; k++) {
        int qi = q0 + k * THREADS;
        qxs[k] = qb[qi * 3 + 0];
        qys[k] = qb[qi * 3 + 1];
        qzs[k] = qb[qi * 3 + 2];
    }
    const ull qx01 = pk2(qxs[0], qxs[1]), qx23 = pk2(qxs[2], qxs[3]);
    const ull qy01 = pk2(qys[0], qys[1]), qy23 = pk2(qys[2], qys[3]);
    const ull qz01 = pk2(qzs[0], qzs[1]), qz23 = pk2(qzs[2], qzs[3]);

    __syncthreads();

    // ---- Pass 1: min distance only (FMNMX), track improving segment ----
    float bd[QPT], prev[QPT];
    int   sg[QPT];
#pragma unroll
    for (int k = 0; k < QPT; k++) { bd[k] = 3.4e38f; prev[k] = 3.4e38f; sg[k] = 0; }

    for (int s = 0; s < NSEG; s++) {
        const int base = s * SEG;
#pragma unroll 8
        for (int t = 0; t < SEG; t++) {
            const int jj = base + t;
            ull nx = sx[jj], ny = sy[jj], nz = sz[jj];
            ull s01 = pdist2(qx01, qy01, qz01, nx, ny, nz);
            ull s23 = pdist2(qx23, qy23, qz23, nx, ny, nz);

            float d0, d1, d2, d3;
            up2(s01, d0, d1);
            up2(s23, d2, d3);
            bd[0] = fminf(bd[0], d0);
            bd[1] = fminf(bd[1], d1);
            bd[2] = fminf(bd[2], d2);
            bd[3] = fminf(bd[3], d3);
        }
        // Strict change => this segment first achieved the current best.
        // Ties (fminf keeps old value) leave sg at the earliest segment.
#pragma unroll
        for (int k = 0; k < QPT; k++) {
            if (bd[k] != prev[k]) { sg[k] = s; prev[k] = bd[k]; }
        }
    }

    // ---- Pass 2: rescan winning segment with the IDENTICAL packed ops ----
    // Bit parity with pass 1 is guaranteed: same inline-asm instructions on the
    // same packed registers; we just extract the lane belonging to query k.
#pragma unroll
    for (int k = 0; k < QPT; k++) {
        const ull qpx = (k < 2) ? qx01 : qx23;
        const ull qpy = (k < 2) ? qy01 : qy23;
        const ull qpz = (k < 2) ? qz01 : qz23;
        const unsigned tbits = __float_as_uint(bd[k]);
        int jbest = 0x7fffffff;

        const int base = sg[k] * SEG;
#pragma unroll 8
        for (int t = 0; t < SEG; t++) {
            const int j = base + t;
            ull s2 = pdist2(qpx, qpy, qpz, sx[j], sy[j], sz[j]);
            float lo, hi;
            up2(s2, lo, hi);
            float d = (k & 1) ? hi : lo;
            if (__float_as_uint(d) == tbits) jbest = min(jbest, j);
        }

        // Safety net (should never fire): bd[k] is the min of exactly these
        // packed values over the whole chunk, so a full scan must find it.
        if (jbest == 0x7fffffff) {
            for (int j = 0; j < JCHUNK; j++) {
                ull s2 = pdist2(qpx, qpy, qpz, sx[j], sy[j], sz[j]);
                float lo, hi;
                up2(s2, lo, hi);
                float d = (k & 1) ? hi : lo;
                if (__float_as_uint(d) == tbits) { jbest = j; break; }
            }
            if (jbest == 0x7fffffff) jbest = 0;  // deterministic last resort
        }

        const int qi = q0 + k * THREADS;
        ull key = ((ull)tbits << 32) | (unsigned)(jbase + jbest);
        g_part[dir][jc][b * NPTS + qi] = key;
    }
}

// Reduce 8 partials per (dir, point); unpack into [dist1|dist2|idx1|idx2].
// Key compare: equal dist bits -> smaller j wins = global first occurrence,
// matching the reference's strict-< merge + first-occurrence argmin.
__global__ void finalize_kernel(float* __restrict__ out) {
    int i = blockIdx.x * blockDim.x + threadIdx.x;
    if (i >= BATCH * NPTS) return;
#pragma unroll
    for (int dir = 0; dir < 2; dir++) {
        ull best = 0xFFFFFFFFFFFFFFFFull;
#pragma unroll
        for (int jc = 0; jc < JSPLIT; jc++) {
            ull v = g_part[dir][jc][i];
            best = (v < best) ? v : best;
        }
        out[dir * BATCH * NPTS + i]       = __uint_as_float((unsigned)(best >> 32));
        out[(2 + dir) * BATCH * NPTS + i] = (float)(int)(best & 0xFFFFFFFFu);
    }
}

extern "C" void kernel_launch(void* const* d_in, const int* in_sizes, int n_in,
                              void* d_out, int out_size) {
    const float* xyz1 = (const float*)d_in[0];
    const float* xyz2 = (const float*)d_in[1];
    float* out = (float*)d_out;

    dim3 grid((NPTS / QTILE) * JSPLIT, BATCH, 2);
    chamfer_kernel<<<grid, THREADS>>>(xyz1, xyz2);

    finalize_kernel<<<(BATCH * NPTS + 255) / 256, 256>>>(out);
}

// round 7
// speedup vs baseline: 1.7870x; 1.7870x over previous
#include <cuda_runtime.h>

#define BATCH   4
#define NPTS    8192
#define THREADS 256
#define QPT     4
#define QTILE   (THREADS * QPT)     // 1024 queries per block
#define JSPLIT  8
#define JCHUNK  (NPTS / JSPLIT)     // 1024 ref points per block (fully smem-resident)

typedef unsigned long long ull;

// Partial results: packed (dist_bits<<32)|global_j per (dir, jc, b*N+q). 4 MB.
__device__ ull g_part[2][JSPLIT][BATCH * NPTS];

// ---- packed fp32x2 helpers (sm_103a). Explicit .rn, no FMA contraction. ----
static __device__ __forceinline__ ull pk2(float lo, float hi) {
    ull r; asm("mov.b64 %0, {%1, %2};" : "=l"(r) : "f"(lo), "f"(hi)); return r;
}
static __device__ __forceinline__ void up2(ull v, float& lo, float& hi) {
    asm("mov.b64 {%0, %1}, %2;" : "=f"(lo), "=f"(hi) : "l"(v));
}
static __device__ __forceinline__ ull add2(ull a, ull b) {
    ull r; asm("add.rn.f32x2 %0, %1, %2;" : "=l"(r) : "l"(a), "l"(b)); return r;
}
static __device__ __forceinline__ ull mul2(ull a, ull b) {
    ull r; asm("mul.rn.f32x2 %0, %1, %2;" : "=l"(r) : "l"(a), "l"(b)); return r;
}

// One fused kernel: blockIdx.z selects direction.
// Grid: x = (NPTS/QTILE)*JSPLIT = 64, y = BATCH, z = 2.
__global__ void __launch_bounds__(THREADS)
chamfer_kernel(const float* __restrict__ xyz1, const float* __restrict__ xyz2)
{
    // Negated, lane-duplicated SoA ref chunk: sx[j] = pk2(-x_j, -x_j). 24 KB.
    __shared__ ull sx[JCHUNK], sy[JCHUNK], sz[JCHUNK];

    const int dir = blockIdx.z;
    const int b   = blockIdx.y;
    const int qt  = blockIdx.x / JSPLIT;
    const int jc  = blockIdx.x % JSPLIT;
    const int tid = threadIdx.x;

    const float* qpts = dir ? xyz2 : xyz1;
    const float* rpts = dir ? xyz1 : xyz2;
    const float* qb = qpts + (size_t)b * NPTS * 3;
    const float* rb = rpts + (size_t)b * NPTS * 3;

    const int jbase = jc * JCHUNK;

    // ---- Stage the full chunk (negated, duplicated) ----
    for (int l = tid; l < JCHUNK; l += THREADS) {
        const float* r = rb + (size_t)(jbase + l) * 3;
        float nx = -r[0], ny = -r[1], nz = -r[2];
        sx[l] = pk2(nx, nx);
        sy[l] = pk2(ny, ny);
        sz[l] = pk2(nz, nz);
    }

    // ---- Load 4 queries per thread (strided), pack as f32x2 pairs ----
    const int q0 = qt * QTILE + tid;
    float qx[QPT], qy[QPT], qz[QPT];
#pragma unroll
    for (int k = 0; k < QPT; k++) {
        int qi = q0 + k * THREADS;
        qx[k] = qb[qi * 3 + 0];
        qy[k] = qb[qi * 3 + 1];
        qz[k] = qb[qi * 3 + 2];
    }
    const ull qx01 = pk2(qx[0], qx[1]), qx23 = pk2(qx[2], qx[3]);
    const ull qy01 = pk2(qy[0], qy[1]), qy23 = pk2(qy[2], qy[3]);
    const ull qz01 = pk2(qz[0], qz[1]), qz23 = pk2(qz[2], qz[3]);

    float bd[QPT];
    int   bj[QPT];
#pragma unroll
    for (int k = 0; k < QPT; k++) { bd[k] = 3.4e38f; bj[k] = 0; }

    __syncthreads();

    // ---- Hot loop: 1 ref x 4 queries per iteration, in-loop argmin ----
#pragma unroll 4
    for (int jj = 0; jj < JCHUNK; jj++) {
        ull nx = sx[jj], ny = sy[jj], nz = sz[jj];

        ull dx01 = add2(qx01, nx), dy01 = add2(qy01, ny), dz01 = add2(qz01, nz);
        ull dx23 = add2(qx23, nx), dy23 = add2(qy23, ny), dz23 = add2(qz23, nz);

        // d = (dx*dx + dy*dy) + dz*dz -- plain .rn mul/add, matches reference order
        ull s01 = add2(add2(mul2(dx01, dx01), mul2(dy01, dy01)), mul2(dz01, dz01));
        ull s23 = add2(add2(mul2(dx23, dx23), mul2(dy23, dy23)), mul2(dz23, dz23));

        float d0, d1, d2, d3;
        up2(s01, d0, d1);
        up2(s23, d2, d3);

        if (d0 < bd[0]) { bd[0] = d0; bj[0] = jj; }
        if (d1 < bd[1]) { bd[1] = d1; bj[1] = jj; }
        if (d2 < bd[2]) { bd[2] = d2; bj[2] = jj; }
        if (d3 < bd[3]) { bd[3] = d3; bj[3] = jj; }
    }

    // ---- Write partials (no atomics; private slot per (dir,jc)) ----
    ull* dst = &g_part[dir][jc][b * NPTS];
#pragma unroll
    for (int k = 0; k < QPT; k++) {
        int qi = q0 + k * THREADS;
        ull key = ((ull)__float_as_uint(bd[k]) << 32) | (unsigned)(jbase + bj[k]);
        dst[qi] = key;
    }
}

// Reduce 8 partials per (dir, point); unpack into [dist1|dist2|idx1|idx2].
// Equal dist bits -> smaller global j wins = reference first-occurrence argmin.
__global__ void finalize_kernel(float* __restrict__ out) {
    int i = blockIdx.x * blockDim.x + threadIdx.x;
    if (i >= BATCH * NPTS) return;
#pragma unroll
    for (int dir = 0; dir < 2; dir++) {
        ull best = 0xFFFFFFFFFFFFFFFFull;
#pragma unroll
        for (int jc = 0; jc < JSPLIT; jc++) {
            ull v = g_part[dir][jc][i];
            best = (v < best) ? v : best;
        }
        out[dir * BATCH * NPTS + i]       = __uint_as_float((unsigned)(best >> 32));
        out[(2 + dir) * BATCH * NPTS + i] = (float)(int)(best & 0xFFFFFFFFu);
    }
}

extern "C" void kernel_launch(void* const* d_in, const int* in_sizes, int n_in,
                              void* d_out, int out_size) {
    const float* xyz1 = (const float*)d_in[0];
    const float* xyz2 = (const float*)d_in[1];
    float* out = (float*)d_out;

    dim3 grid((NPTS / QTILE) * JSPLIT, BATCH, 2);
    chamfer_kernel<<<grid, THREADS>>>(xyz1, xyz2);

    finalize_kernel<<<(BATCH * NPTS + 255) / 256, 256>>>(out);
}